// round 1
// baseline (speedup 1.0000x reference)
#include <cuda_runtime.h>
#include <cstdint>
#include <cstddef>

// ---------------------------------------------------------------------------
// QAOA-style diff quantum simulator, N=18 qubits, B=8, 4 layers.
//
// Key facts exploited:
//  * hp_diag[b][d] = #cut edges  -> small integer in [0,153], stored as u8.
//  * phase exp(-i*hp) is identical every layer -> 256-entry smem table.
//  * RX rotations on different bits commute -> split 18 bits across two
//    alternating block layouts; 4 layers + energy = 5 state passes total.
//  * per block: 2^14 amplitudes, 512 threads x 32 amps in registers,
//    3 register residencies (bits 0-4 / 5-9 / 9-13), 2 smem exchanges.
// ---------------------------------------------------------------------------

namespace {
constexpr int NQ   = 18;
constexpr int QDIM = 1 << NQ;            // 262144
constexpr int NB   = 8;
constexpr int NL   = 4;
constexpr int TPB  = 512;
constexpr int RPT  = 32;                 // amplitudes per thread (5 bits)
constexpr int CHUNK = TPB * RPT;         // 16384 amplitudes per block
constexpr int BLOCKS = NB * (QDIM / CHUNK);  // 128
constexpr size_t SMEM_BYTES = (size_t)CHUNK * sizeof(float2); // 131072
}

__device__ __align__(256) float2 g_state[(size_t)NB * QDIM]; // 16 MB
__device__ __align__(16) unsigned char g_hp[(size_t)NB * QDIM]; // 2 MB
__device__ float g_partial[BLOCKS];

// --------------------------- helpers ---------------------------------------

__device__ __forceinline__ int swz(int i) { return i ^ ((i >> 5) & 31); }

// local-index -> global basis-state index within batch
template<bool G>
__device__ __forceinline__ int dmap(int cb, int local) {
  if (G)  // gathered: local bits 10..13 -> global 14..17, cb -> global 10..13
    return ((local >> 10) << 14) | (cb << 10) | (local & 1023);
  else    // contiguous: cb -> global 14..17
    return (cb << 14) | local;
}

// residency mappings: local index covered by (tid, r)
__device__ __forceinline__ int locM0(int tid, int r) { return (tid << 5) | r; }                     // regs = bits 0..4
__device__ __forceinline__ int locM1(int tid, int r) { return ((tid >> 5) << 10) | (r << 5) | (tid & 31); } // regs = bits 5..9
__device__ __forceinline__ int locM2(int tid, int r) { return (r << 9) | tid; }                     // regs = bits 9..13

// RX pair rotation: new0 = c*s0 - i s*s1 ; new1 = c*s1 - i s*s0
__device__ __forceinline__ void rotp(float2& x, float2& y, float c, float s) {
  float nx0 = fmaf(c, x.x,  s * y.y);
  float nx1 = fmaf(c, x.y, -s * y.x);
  float ny0 = fmaf(c, y.x,  s * x.y);
  float ny1 = fmaf(c, y.y, -s * x.x);
  x = make_float2(nx0, nx1);
  y = make_float2(ny0, ny1);
}

template<int P>
__device__ __forceinline__ void btf(float2* a, float c, float s) {
#pragma unroll
  for (int h = 0; h < RPT / 2; h++) {
    int i0 = ((h >> P) << (P + 1)) | (h & ((1 << P) - 1));
    rotp(a[i0], a[i0 | (1 << P)], c, s);
  }
}

__device__ __forceinline__ void btf_04(float2* a, float c, float s) {
  btf<0>(a, c, s); btf<1>(a, c, s); btf<2>(a, c, s); btf<3>(a, c, s); btf<4>(a, c, s);
}
__device__ __forceinline__ void btf_14(float2* a, float c, float s) {
  btf<1>(a, c, s); btf<2>(a, c, s); btf<3>(a, c, s); btf<4>(a, c, s);
}
__device__ __forceinline__ void btf_03(float2* a, float c, float s) {
  btf<0>(a, c, s); btf<1>(a, c, s); btf<2>(a, c, s); btf<3>(a, c, s);
}

// --------------------------- hp (cut-count) kernel --------------------------

__global__ void hp_kernel(const float* __restrict__ adj) {
  __shared__ int rm[NQ];
  __shared__ int sk[NQ];
  __shared__ int sne;
  const int b = blockIdx.x >> 7;              // 128 blocks per batch
  const int dbase = (blockIdx.x & 127) << 11; // 2048 states per block
  const int tid = threadIdx.x;

  if (tid < NQ) {
    int m = 0;
    const float* row = adj + (size_t)b * NQ * NQ + tid * NQ;
    for (int v = tid + 1; v < NQ; v++)
      if (row[v] > 0.5f) m |= 1 << (17 - v);
    rm[tid] = m;
    sk[tid] = __popc(m);
  }
  __syncthreads();
  if (tid == 0) {
    int ne = 0;
    for (int u = 0; u < NQ; u++) ne += sk[u];
    sne = ne;
  }
  __syncthreads();
  const int ne = sne;
  unsigned char* hb = g_hp + (size_t)b * QDIM + dbase;
#pragma unroll
  for (int i = 0; i < 8; i++) {
    int d = dbase + tid + i * 256;
    int cross = 0;
#pragma unroll
    for (int u = 0; u < NQ; u++) {
      int m = rm[u];
      int t = sk[u] - 2 * __popc(d & m);
      cross += ((d >> (17 - u)) & 1) ? -t : t;
    }
    hb[tid + i * 256] = (unsigned char)((ne - cross) >> 1);
  }
}

// --------------------------- main pass kernel -------------------------------
// MAINM: 0=none, 1=up (M0->M1->M2, used for init pass), 2=down (M2->M1->M0)

template<bool GATHER, bool INIT, bool PRE, bool PHASE, int MAINM, bool ENERGY>
__global__ void __launch_bounds__(TPB, 1)
qaoa_pass(const float* __restrict__ betas, int pre_layer, int main_layer) {
  extern __shared__ float2 sh[];
  __shared__ float2 ph_tab[256];
  __shared__ float red[TPB / 32];

  const int tid = threadIdx.x;
  const int b = blockIdx.x >> 4;
  const int cb = blockIdx.x & 15;

  if (PHASE) {
    if (tid < 256) {
      float sv, cv;
      sincosf((float)tid, &sv, &cv);
      ph_tab[tid] = make_float2(cv, sv);   // exp(-ik) = (cos k, -sin k); sign in apply
    }
  }
  float c_pre = 1.f, s_pre = 0.f, c_m = 1.f, s_m = 0.f;
  if (PRE)       { float bt = betas[b * NL + pre_layer];  sincosf(bt, &s_pre, &c_pre); }
  if (MAINM)     { float bt = betas[b * NL + main_layer]; sincosf(bt, &s_m,   &c_m); }
  if (PHASE) __syncthreads();

  const unsigned char* hpb = g_hp + (size_t)b * QDIM;
  float2* stb = g_state + (size_t)b * QDIM;

  float2 a[RPT];

  // ---- load / init (INIT starts in M0; everything else starts in M2) ----
  if (INIT) {
    const float inv = 0.001953125f;  // 1/sqrt(2^18)
#pragma unroll
    for (int r = 0; r < RPT; r++) a[r] = make_float2(inv, 0.f);
  } else {
#pragma unroll
    for (int r = 0; r < RPT; r++)
      a[r] = stb[dmap<GATHER>(cb, locM2(tid, r))];
  }

  // ---- finish previous layer: rotate local bits 10..13 (r-bits 1..4 in M2)
  if (PRE) btf_14(a, c_pre, s_pre);

  // ---- diagonal phase exp(-i*hp) ----
  if (PHASE) {
    if (INIT) {  // M0 layout: 32 contiguous hp bytes per thread, 2x LDG.128
      const uint4* hv = reinterpret_cast<const uint4*>(hpb + dmap<GATHER>(cb, tid << 5));
      uint4 h0 = hv[0], h1 = hv[1];
      unsigned int w[8] = {h0.x, h0.y, h0.z, h0.w, h1.x, h1.y, h1.z, h1.w};
#pragma unroll
      for (int r = 0; r < RPT; r++) {
        int k = (w[r >> 2] >> ((r & 3) << 3)) & 0xFF;
        float2 ph = ph_tab[k];
        a[r] = make_float2(fmaf(a[r].x, ph.x,  a[r].y * ph.y),
                           fmaf(a[r].y, ph.x, -a[r].x * ph.y));
      }
    } else {     // M2 layout: byte loads, warp-coalesced per r
#pragma unroll
      for (int r = 0; r < RPT; r++) {
        int k = hpb[dmap<GATHER>(cb, locM2(tid, r))];
        float2 ph = ph_tab[k];
        a[r] = make_float2(fmaf(a[r].x, ph.x,  a[r].y * ph.y),
                           fmaf(a[r].y, ph.x, -a[r].x * ph.y));
      }
    }
  }

  if (MAINM == 1) {
    // ---- UP: M0 {bits 0..4} -> M1 {5..9} -> M2 {10..13} ----
    btf_04(a, c_m, s_m);
    __syncthreads();
#pragma unroll
    for (int r = 0; r < RPT; r++) sh[swz(locM0(tid, r))] = a[r];
    __syncthreads();
#pragma unroll
    for (int r = 0; r < RPT; r++) a[r] = sh[swz(locM1(tid, r))];
    btf_04(a, c_m, s_m);
    __syncthreads();
#pragma unroll
    for (int r = 0; r < RPT; r++) sh[swz(locM1(tid, r))] = a[r];
    __syncthreads();
#pragma unroll
    for (int r = 0; r < RPT; r++) a[r] = sh[swz(locM2(tid, r))];
    btf_14(a, c_m, s_m);  // skip r-bit0 = local bit 9 (done in M1)
#pragma unroll
    for (int r = 0; r < RPT; r++)
      stb[dmap<GATHER>(cb, locM2(tid, r))] = a[r];
  } else if (MAINM == 2) {
    // ---- DOWN: M2 {bits 9..13} -> M1 {5..8} -> M0 {0..4} ----
    btf_04(a, c_m, s_m);
    __syncthreads();
#pragma unroll
    for (int r = 0; r < RPT; r++) sh[swz(locM2(tid, r))] = a[r];
    __syncthreads();
#pragma unroll
    for (int r = 0; r < RPT; r++) a[r] = sh[swz(locM1(tid, r))];
    btf_03(a, c_m, s_m);  // skip r-bit4 = local bit 9 (done in M2)
    __syncthreads();
#pragma unroll
    for (int r = 0; r < RPT; r++) sh[swz(locM1(tid, r))] = a[r];
    __syncthreads();
#pragma unroll
    for (int r = 0; r < RPT; r++) a[r] = sh[swz(locM0(tid, r))];
    btf_04(a, c_m, s_m);
    // vectorized contiguous store (32 consecutive amplitudes per thread)
    float4* dst = reinterpret_cast<float4*>(stb + dmap<GATHER>(cb, tid << 5));
#pragma unroll
    for (int i = 0; i < RPT / 2; i++)
      dst[i] = make_float4(a[2 * i].x, a[2 * i].y, a[2 * i + 1].x, a[2 * i + 1].y);
  }

  if (ENERGY) {
    float e = 0.f;
#pragma unroll
    for (int r = 0; r < RPT; r++) {
      int k = hpb[dmap<GATHER>(cb, locM2(tid, r))];
      e += (a[r].x * a[r].x + a[r].y * a[r].y) * (float)k;
    }
#pragma unroll
    for (int o = 16; o; o >>= 1) e += __shfl_down_sync(0xffffffffu, e, o);
    if ((tid & 31) == 0) red[tid >> 5] = e;
    __syncthreads();
    if (tid == 0) {
      float t = 0.f;
#pragma unroll
      for (int i = 0; i < TPB / 32; i++) t += red[i];
      g_partial[blockIdx.x] = t;
    }
  }
}

// --------------------------- final deterministic reduce ---------------------

__global__ void k_finish(float* __restrict__ out) {
  int b = threadIdx.x;
  if (b < NB) {
    float t = 0.f;
#pragma unroll
    for (int i = 0; i < 16; i++) t += g_partial[b * 16 + i];
    out[b] = t;
  }
}

// --------------------------- launch ----------------------------------------

extern "C" void kernel_launch(void* const* d_in, const int* in_sizes, int n_in,
                              void* d_out, int out_size) {
  const float* betas = (const float*)d_in[0];
  const float* adj   = (const float*)d_in[1];
  if (n_in >= 2 && in_sizes[0] != NB * NL) {  // defensive input-order check
    betas = (const float*)d_in[1];
    adj   = (const float*)d_in[0];
  }
  float* out = (float*)d_out;
  (void)out_size;

  // instantiations:
  // P1: contiguous, init + phase + R1{bits 0..13}            (up)
  auto kP1 = qaoa_pass<false, true,  false, true, 1, false>;
  // P2/P4: gathered, R_t{14..17} + phase + R_{t+1}{0..9,14..17} (down)
  auto kPB = qaoa_pass<true,  false, true,  true, 2, false>;
  // P3: contiguous, R_t{10..13} + phase + R_{t+1}{0..13}     (down)
  auto kPA = qaoa_pass<false, false, true,  true, 2, false>;
  // P5: contiguous, R4{10..13} + energy
  auto kP5 = qaoa_pass<false, false, true,  false, 0, true>;

  cudaFuncSetAttribute(kP1, cudaFuncAttributeMaxDynamicSharedMemorySize, (int)SMEM_BYTES);
  cudaFuncSetAttribute(kPB, cudaFuncAttributeMaxDynamicSharedMemorySize, (int)SMEM_BYTES);
  cudaFuncSetAttribute(kPA, cudaFuncAttributeMaxDynamicSharedMemorySize, (int)SMEM_BYTES);

  hp_kernel<<<NB * 128, 256>>>(adj);
  kP1<<<BLOCKS, TPB, SMEM_BYTES>>>(betas, -1, 0);
  kPB<<<BLOCKS, TPB, SMEM_BYTES>>>(betas, 0, 1);
  kPA<<<BLOCKS, TPB, SMEM_BYTES>>>(betas, 1, 2);
  kPB<<<BLOCKS, TPB, SMEM_BYTES>>>(betas, 2, 3);
  kP5<<<BLOCKS, TPB, 0>>>(betas, 3, -1);
  k_finish<<<1, 32>>>(out);
}